// round 12
// baseline (speedup 1.0000x reference)
#include <cuda_runtime.h>
#include <cuda_bf16.h>
#include <cuda_fp16.h>

#define N_NODES 50000
#define N_EDGES 800000
#define F_IN    256
#define HDIM    128
#define NB_SCAN ((N_NODES + 255) / 256)   // 196

// Scratch (device globals)
__device__ float  g_buf0[N_NODES * HDIM];               // fp32 intermediate
__device__ __align__(16) __half g_h16[N_NODES * HDIM];  // fp16 GEMM output
__device__ int    g_deg[N_NODES];
__device__ int    g_rowptr[N_NODES];
__device__ int    g_cursor[N_NODES];
__device__ int    g_csrsrc[N_EDGES];
__device__ float  g_dinv[N_NODES];
__device__ int    g_bsum[256];

// Side stream + fork/join events, created once at static init.
static cudaStream_t g_side = nullptr;
static cudaEvent_t  g_ev_fork = nullptr, g_ev_join = nullptr;
namespace {
struct StreamInit {
    StreamInit() {
        cudaStreamCreateWithFlags(&g_side, cudaStreamNonBlocking);
        cudaEventCreateWithFlags(&g_ev_fork, cudaEventDisableTiming);
        cudaEventCreateWithFlags(&g_ev_join, cudaEventDisableTiming);
    }
};
static StreamInit g_stream_init;
}

// ---------------------------------------------------------------- degree
__global__ void zero_kernel() {
    int i = blockIdx.x * blockDim.x + threadIdx.x;
    if (i < N_NODES) g_deg[i] = 0;
}

__global__ void count_deg_kernel(const int* __restrict__ dst) {
    int i = blockIdx.x * blockDim.x + threadIdx.x;
    if (i < N_EDGES) atomicAdd(&g_deg[dst[i]], 1);
}

// ------------------------------------------------- scan (2 kernels)
__global__ void __launch_bounds__(256) scan_local_kernel() {
    __shared__ int wsum[8];
    int tid = threadIdx.x, lane = tid & 31, wid = tid >> 5;
    int i = blockIdx.x * 256 + tid;
    int v = (i < N_NODES) ? g_deg[i] : 0;
    if (i < N_NODES) {
        g_dinv[i] = rsqrtf((float)(v + 1));
        g_cursor[i] = 0;
    }
    int incl = v;
#pragma unroll
    for (int off = 1; off < 32; off <<= 1) {
        int t = __shfl_up_sync(0xffffffffu, incl, off);
        if (lane >= off) incl += t;
    }
    if (lane == 31) wsum[wid] = incl;
    __syncthreads();
    if (wid == 0 && lane < 8) {
        int w = wsum[lane];
#pragma unroll
        for (int off = 1; off < 8; off <<= 1) {
            int t = __shfl_up_sync(0xffu, w, off);
            if (lane >= off) w += t;
        }
        wsum[lane] = w;
    }
    __syncthreads();
    int excl = incl - v + (wid ? wsum[wid - 1] : 0);
    if (i < N_NODES) g_rowptr[i] = excl;   // block-local exclusive
    if (tid == 255) g_bsum[blockIdx.x] = wsum[7];
}

__global__ void __launch_bounds__(256) scan_block_kernel() {
    __shared__ int wsum[8];
    int tid = threadIdx.x, lane = tid & 31, wid = tid >> 5;
    int v = (tid < NB_SCAN) ? g_bsum[tid] : 0;
    int incl = v;
#pragma unroll
    for (int off = 1; off < 32; off <<= 1) {
        int t = __shfl_up_sync(0xffffffffu, incl, off);
        if (lane >= off) incl += t;
    }
    if (lane == 31) wsum[wid] = incl;
    __syncthreads();
    if (wid == 0 && lane < 8) {
        int w = wsum[lane];
#pragma unroll
        for (int off = 1; off < 8; off <<= 1) {
            int t = __shfl_up_sync(0xffu, w, off);
            if (lane >= off) w += t;
        }
        wsum[lane] = w;
    }
    __syncthreads();
    int excl = incl - v + (wid ? wsum[wid - 1] : 0);
    if (tid < NB_SCAN) g_bsum[tid] = excl;
}

__global__ void fill_csr_kernel(const int* __restrict__ src,
                                const int* __restrict__ dst) {
    int i = blockIdx.x * blockDim.x + threadIdx.x;
    if (i < N_EDGES) {
        int d = dst[i];
        int pos = g_rowptr[d] + g_bsum[d >> 8] + atomicAdd(&g_cursor[d], 1);
        g_csrsrc[pos] = src[i];
    }
}

__device__ __forceinline__ int row_start(int node) {
    return g_rowptr[node] + g_bsum[node >> 8];
}

// ---------------------------------------------------------------- MMA GEMM
// C16[M,128] (fp16) = A[M,K] @ B[K,128] fp32, via bf16 2-split (3 MMAs).

__device__ __forceinline__ void ldsm4(unsigned& r0, unsigned& r1,
                                      unsigned& r2, unsigned& r3,
                                      const void* p) {
    unsigned a = (unsigned)__cvta_generic_to_shared(p);
    asm volatile("ldmatrix.sync.aligned.m8n8.x4.shared.b16 {%0,%1,%2,%3}, [%4];"
                 : "=r"(r0), "=r"(r1), "=r"(r2), "=r"(r3) : "r"(a));
}

__device__ __forceinline__ void ldsm4t(unsigned& r0, unsigned& r1,
                                       unsigned& r2, unsigned& r3,
                                       const void* p) {
    unsigned a = (unsigned)__cvta_generic_to_shared(p);
    asm volatile("ldmatrix.sync.aligned.m8n8.x4.trans.shared.b16 {%0,%1,%2,%3}, [%4];"
                 : "=r"(r0), "=r"(r1), "=r"(r2), "=r"(r3) : "r"(a));
}

__device__ __forceinline__ void mma16816(float* d, const unsigned* a,
                                         unsigned b0, unsigned b1) {
    asm volatile(
        "mma.sync.aligned.m16n8k16.row.col.f32.bf16.bf16.f32 "
        "{%0,%1,%2,%3}, {%4,%5,%6,%7}, {%8,%9}, {%0,%1,%2,%3};\n"
        : "+f"(d[0]), "+f"(d[1]), "+f"(d[2]), "+f"(d[3])
        : "r"(a[0]), "r"(a[1]), "r"(a[2]), "r"(a[3]), "r"(b0), "r"(b1));
}

__device__ __forceinline__ void split2(float x, float y,
                                       __nv_bfloat162& hi, __nv_bfloat162& lo) {
    __nv_bfloat16 hx = __float2bfloat16(x);
    __nv_bfloat16 hy = __float2bfloat16(y);
    __nv_bfloat16 lx = __float2bfloat16(x - __bfloat162float(hx));
    __nv_bfloat16 ly = __float2bfloat16(y - __bfloat162float(hy));
    hi = __halves2bfloat162(hx, hy);
    lo = __halves2bfloat162(lx, ly);
}

#define SA_LD 24   // 16 + 8 pad
#define SB_LD 136  // 128 + 8 pad

__global__ void __launch_bounds__(256) gemm_bf16x3(
    const float* __restrict__ A, const float* __restrict__ B,
    __half* __restrict__ C16, int M, int K)
{
    __shared__ __align__(16) __nv_bfloat16 sAh[2][128][SA_LD];
    __shared__ __align__(16) __nv_bfloat16 sAl[2][128][SA_LD];
    __shared__ __align__(16) __nv_bfloat16 sBh[2][16][SB_LD];
    __shared__ __align__(16) __nv_bfloat16 sBl[2][16][SB_LD];

    const int tid  = threadIdx.x;
    const int lane = tid & 31;
    const int wid  = tid >> 5;
    const int bm   = blockIdx.x * 128;

    const int wm = (wid >> 1) * 32;
    const int wn = (wid & 1) * 64;

    const int arow = tid >> 1;
    const int acg  = (tid & 1) * 8;
    const int brow = tid >> 4;
    const int bcg  = (tid & 15) * 8;

    const bool avalid = (bm + arow) < M;

    const int a_r = ((lane >> 3) & 1) * 8 + (lane & 7);
    const int a_c = (lane >> 4) * 8;
    const int b_k = ((lane >> 3) & 1) * 8 + (lane & 7);
    const int b_n = (lane >> 4) * 8;

    float acc[2][8][4];
#pragma unroll
    for (int i = 0; i < 2; i++)
#pragma unroll
        for (int j = 0; j < 8; j++)
#pragma unroll
            for (int q = 0; q < 4; q++) acc[i][j][q] = 0.0f;

    const int nt = K >> 4;

    {
        float4 a0 = make_float4(0.f,0.f,0.f,0.f), a1 = a0;
        if (avalid) {
            a0 = *(const float4*)(A + (size_t)(bm + arow) * K + acg);
            a1 = *(const float4*)(A + (size_t)(bm + arow) * K + acg + 4);
        }
        float4 b0 = *(const float4*)(B + (size_t)brow * 128 + bcg);
        float4 b1 = *(const float4*)(B + (size_t)brow * 128 + bcg + 4);
        __nv_bfloat162 h, l;
        split2(a0.x, a0.y, h, l);
        *(__nv_bfloat162*)&sAh[0][arow][acg+0] = h; *(__nv_bfloat162*)&sAl[0][arow][acg+0] = l;
        split2(a0.z, a0.w, h, l);
        *(__nv_bfloat162*)&sAh[0][arow][acg+2] = h; *(__nv_bfloat162*)&sAl[0][arow][acg+2] = l;
        split2(a1.x, a1.y, h, l);
        *(__nv_bfloat162*)&sAh[0][arow][acg+4] = h; *(__nv_bfloat162*)&sAl[0][arow][acg+4] = l;
        split2(a1.z, a1.w, h, l);
        *(__nv_bfloat162*)&sAh[0][arow][acg+6] = h; *(__nv_bfloat162*)&sAl[0][arow][acg+6] = l;
        split2(b0.x, b0.y, h, l);
        *(__nv_bfloat162*)&sBh[0][brow][bcg+0] = h; *(__nv_bfloat162*)&sBl[0][brow][bcg+0] = l;
        split2(b0.z, b0.w, h, l);
        *(__nv_bfloat162*)&sBh[0][brow][bcg+2] = h; *(__nv_bfloat162*)&sBl[0][brow][bcg+2] = l;
        split2(b1.x, b1.y, h, l);
        *(__nv_bfloat162*)&sBh[0][brow][bcg+4] = h; *(__nv_bfloat162*)&sBl[0][brow][bcg+4] = l;
        split2(b1.z, b1.w, h, l);
        *(__nv_bfloat162*)&sBh[0][brow][bcg+6] = h; *(__nv_bfloat162*)&sBl[0][brow][bcg+6] = l;
    }
    __syncthreads();

    for (int t = 0; t < nt; t++) {
        const int cur = t & 1;

        float4 a0, a1, b0, b1;
        const bool more = (t + 1) < nt;
        if (more) {
            int k0 = (t + 1) << 4;
            a0 = make_float4(0.f,0.f,0.f,0.f); a1 = a0;
            if (avalid) {
                a0 = *(const float4*)(A + (size_t)(bm + arow) * K + k0 + acg);
                a1 = *(const float4*)(A + (size_t)(bm + arow) * K + k0 + acg + 4);
            }
            b0 = *(const float4*)(B + (size_t)(k0 + brow) * 128 + bcg);
            b1 = *(const float4*)(B + (size_t)(k0 + brow) * 128 + bcg + 4);
        }

        unsigned ah[2][4], al[2][4];
#pragma unroll
        for (int tm = 0; tm < 2; tm++) {
            ldsm4(ah[tm][0], ah[tm][1], ah[tm][2], ah[tm][3],
                  &sAh[cur][wm + tm*16 + a_r][a_c]);
            ldsm4(al[tm][0], al[tm][1], al[tm][2], al[tm][3],
                  &sAl[cur][wm + tm*16 + a_r][a_c]);
        }
#pragma unroll
        for (int np = 0; np < 4; np++) {
            unsigned bh[4], bl[4];
            int n0 = wn + np * 16;
            ldsm4t(bh[0], bh[1], bh[2], bh[3], &sBh[cur][b_k][n0 + b_n]);
            ldsm4t(bl[0], bl[1], bl[2], bl[3], &sBl[cur][b_k][n0 + b_n]);
#pragma unroll
            for (int tm = 0; tm < 2; tm++) {
#pragma unroll
                for (int h = 0; h < 2; h++) {
                    float* d = acc[tm][np * 2 + h];
                    mma16816(d, ah[tm], bh[2*h], bh[2*h + 1]);
                    mma16816(d, ah[tm], bl[2*h], bl[2*h + 1]);
                    mma16816(d, al[tm], bh[2*h], bh[2*h + 1]);
                }
            }
        }

        if (more) {
            const int nxt = cur ^ 1;
            __nv_bfloat162 h, l;
            split2(a0.x, a0.y, h, l);
            *(__nv_bfloat162*)&sAh[nxt][arow][acg+0] = h; *(__nv_bfloat162*)&sAl[nxt][arow][acg+0] = l;
            split2(a0.z, a0.w, h, l);
            *(__nv_bfloat162*)&sAh[nxt][arow][acg+2] = h; *(__nv_bfloat162*)&sAl[nxt][arow][acg+2] = l;
            split2(a1.x, a1.y, h, l);
            *(__nv_bfloat162*)&sAh[nxt][arow][acg+4] = h; *(__nv_bfloat162*)&sAl[nxt][arow][acg+4] = l;
            split2(a1.z, a1.w, h, l);
            *(__nv_bfloat162*)&sAh[nxt][arow][acg+6] = h; *(__nv_bfloat162*)&sAl[nxt][arow][acg+6] = l;
            split2(b0.x, b0.y, h, l);
            *(__nv_bfloat162*)&sBh[nxt][brow][bcg+0] = h; *(__nv_bfloat162*)&sBl[nxt][brow][bcg+0] = l;
            split2(b0.z, b0.w, h, l);
            *(__nv_bfloat162*)&sBh[nxt][brow][bcg+2] = h; *(__nv_bfloat162*)&sBl[nxt][brow][bcg+2] = l;
            split2(b1.x, b1.y, h, l);
            *(__nv_bfloat162*)&sBh[nxt][brow][bcg+4] = h; *(__nv_bfloat162*)&sBl[nxt][brow][bcg+4] = l;
            split2(b1.z, b1.w, h, l);
            *(__nv_bfloat162*)&sBh[nxt][brow][bcg+6] = h; *(__nv_bfloat162*)&sBl[nxt][brow][bcg+6] = l;
        }
        __syncthreads();
    }

    const int g = lane >> 2;
    const int tq = lane & 3;
#pragma unroll
    for (int tm = 0; tm < 2; tm++) {
        int r0 = bm + wm + tm * 16 + g;
        int r1 = r0 + 8;
#pragma unroll
        for (int n8 = 0; n8 < 8; n8++) {
            int col = wn + n8 * 8 + tq * 2;
            float* d = acc[tm][n8];
            if (r0 < M)
                *(__half2*)(C16 + (size_t)r0 * 128 + col) = __floats2half2_rn(d[0], d[1]);
            if (r1 < M)
                *(__half2*)(C16 + (size_t)r1 * 128 + col) = __floats2half2_rn(d[2], d[3]);
        }
    }
}

// ---------------------------------------------------------------- gather
// 2 nodes per warp, 16 lanes per node; fp16 rows read as uint4 (8 halves).
// Warp-uniform loop: both half-warps iterate to the max of their two degree
// counts; out-of-range lanes carry s=0, nm=0 (reads row 0, adds 0).

__device__ __forceinline__ void unpack8(const uint4& u, float* v) {
    float2 f;
    f = __half22float2(*(const __half2*)&u.x); v[0] = f.x; v[1] = f.y;
    f = __half22float2(((const __half2*)&u.x)[1]); v[2] = f.x; v[3] = f.y;
    f = __half22float2(*(const __half2*)&u.z); v[4] = f.x; v[5] = f.y;
    f = __half22float2(((const __half2*)&u.z)[1]); v[6] = f.x; v[7] = f.y;
}

__global__ void gather_relu_kernel(const uint4* __restrict__ h16,  // [N][16]
                                   float* __restrict__ out,
                                   const float* __restrict__ bias)
{
    int w = (blockIdx.x * blockDim.x + threadIdx.x) >> 5;
    int lane = threadIdx.x & 31;
    int grp = lane >> 4, gl = lane & 15;
    int node = w * 2 + grp;
    if (node >= N_NODES) return;   // N_NODES even: whole warp exits together

    float dd = g_dinv[node];
    float v[8], acc[8];
    unpack8(__ldg(h16 + (size_t)node * 16 + gl), v);
    float w0 = dd * dd;
#pragma unroll
    for (int i = 0; i < 8; i++) acc[i] = v[i] * w0;

    int start = row_start(node);
    int cnt   = g_deg[node];
    int cnt_other = __shfl_xor_sync(0xffffffffu, cnt, 16);
    int cnt_max = cnt > cnt_other ? cnt : cnt_other;   // warp-uniform

    for (int base = 0; base < cnt_max; base += 16) {
        int rem = cnt - base;
        int s = 0; float nm = 0.f;
        if (gl < rem) {   // also false when rem <= 0
            s  = __ldg(g_csrsrc + start + base + gl);
            nm = g_dinv[s] * dd;
        }
#pragma unroll 4
        for (int j = 0; j < 16; j++) {
            int sl = (lane & 16) + j;
            int   sj = __shfl_sync(0xffffffffu, s,  sl);
            float nj = __shfl_sync(0xffffffffu, nm, sl);
            float vv[8];
            unpack8(__ldg(h16 + (size_t)sj * 16 + gl), vv);
#pragma unroll
            for (int i = 0; i < 8; i++) acc[i] += vv[i] * nj;
        }
    }

    int c = gl << 3;
#pragma unroll
    for (int i = 0; i < 8; i++)
        acc[i] = fmaxf(acc[i] + __ldg(bias + c + i), 0.f);
    float* o = out + (size_t)node * 128 + c;
    *(float4*)(o)     = make_float4(acc[0], acc[1], acc[2], acc[3]);
    *(float4*)(o + 4) = make_float4(acc[4], acc[5], acc[6], acc[7]);
}

// ------------------------------------------- gather L2 + finalize (fused)
__global__ void gather_final_kernel(const uint4* __restrict__ h16,
                                    const float* __restrict__ b2,
                                    const float* __restrict__ Wh1,
                                    const float* __restrict__ bh1,
                                    const float* __restrict__ Wh2,
                                    const float* __restrict__ bh2,
                                    float* __restrict__ out1,
                                    float* __restrict__ out2,
                                    float* __restrict__ outh)
{
    int w = (blockIdx.x * blockDim.x + threadIdx.x) >> 5;
    int lane = threadIdx.x & 31;
    int grp = lane >> 4, gl = lane & 15;
    int node = w * 2 + grp;
    if (node >= N_NODES) return;

    float dd = g_dinv[node];
    float v[8], acc[8];
    unpack8(__ldg(h16 + (size_t)node * 16 + gl), v);
    float w0 = dd * dd;
#pragma unroll
    for (int i = 0; i < 8; i++) acc[i] = v[i] * w0;

    int start = row_start(node);
    int cnt   = g_deg[node];
    int cnt_other = __shfl_xor_sync(0xffffffffu, cnt, 16);
    int cnt_max = cnt > cnt_other ? cnt : cnt_other;

    for (int base = 0; base < cnt_max; base += 16) {
        int rem = cnt - base;
        int s = 0; float nm = 0.f;
        if (gl < rem) {
            s  = __ldg(g_csrsrc + start + base + gl);
            nm = g_dinv[s] * dd;
        }
#pragma unroll 4
        for (int j = 0; j < 16; j++) {
            int sl = (lane & 16) + j;
            int   sj = __shfl_sync(0xffffffffu, s,  sl);
            float nj = __shfl_sync(0xffffffffu, nm, sl);
            float vv[8];
            unpack8(__ldg(h16 + (size_t)sj * 16 + gl), vv);
#pragma unroll
            for (int i = 0; i < 8; i++) acc[i] += vv[i] * nj;
        }
    }

    int c = gl << 3;
#pragma unroll
    for (int i = 0; i < 8; i++) acc[i] += __ldg(b2 + c + i);

    float* oh = outh + (size_t)node * 128 + c;
    *(float4*)(oh)     = make_float4(acc[0], acc[1], acc[2], acc[3]);
    *(float4*)(oh + 4) = make_float4(acc[4], acc[5], acc[6], acc[7]);

    float p[7];
#pragma unroll
    for (int j = 0; j < 4; j++) {
        float t = 0.f;
#pragma unroll
        for (int i = 0; i < 8; i++) t += acc[i] * __ldg(Wh1 + (c + i) * 4 + j);
        p[j] = t;
    }
#pragma unroll
    for (int j = 0; j < 3; j++) {
        float t = 0.f;
#pragma unroll
        for (int i = 0; i < 8; i++) t += acc[i] * __ldg(Wh2 + (c + i) * 3 + j);
        p[4 + j] = t;
    }
    // reduce across the 16 lanes of this group (xor < 16 stays in group)
#pragma unroll
    for (int j = 0; j < 7; j++) {
#pragma unroll
        for (int off = 8; off > 0; off >>= 1)
            p[j] += __shfl_xor_sync(0xffffffffu, p[j], off);
    }
    if (gl == 0) {
#pragma unroll
        for (int j = 0; j < 4; j++) out1[(size_t)node * 4 + j] = p[j] + __ldg(bh1 + j);
#pragma unroll
        for (int j = 0; j < 3; j++) out2[(size_t)node * 3 + j] = p[4 + j] + __ldg(bh2 + j);
    }
}

// ---------------------------------------------------------------- launch
extern "C" void kernel_launch(void* const* d_in, const int* in_sizes, int n_in,
                              void* d_out, int out_size)
{
    const float* x   = (const float*)d_in[0];
    const int*   ei  = (const int*)d_in[1];        // [2, E]
    const float* W1  = (const float*)d_in[2];
    const float* b1  = (const float*)d_in[3];
    const float* W2  = (const float*)d_in[4];
    const float* b2  = (const float*)d_in[5];
    const float* Wh1 = (const float*)d_in[6];
    const float* bh1 = (const float*)d_in[7];
    const float* Wh2 = (const float*)d_in[8];
    const float* bh2 = (const float*)d_in[9];

    const int* src = ei;
    const int* dst = ei + N_EDGES;

    float* out  = (float*)d_out;
    float* out1 = out;                                    // [N, 4]
    float* out2 = out + (size_t)N_NODES * 4;              // [N, 3]
    float* outh = out + (size_t)N_NODES * 7;              // [N, 128]

    float* B0;   cudaGetSymbolAddress((void**)&B0, g_buf0);
    __half* H16; cudaGetSymbolAddress((void**)&H16, g_h16);

    const int T = 256;
    int gNodes  = (N_NODES + T - 1) / T;
    int gEdges  = (N_EDGES + T - 1) / T;
    int gWarp2  = (((N_NODES + 1) / 2) * 32 + T - 1) / T;   // 2 nodes per warp
    int gGemm   = (N_NODES + 127) / 128;

    // Fork: CSR build on side stream, GEMM1 on main stream (independent).
    cudaEventRecord(g_ev_fork, 0);
    cudaStreamWaitEvent(g_side, g_ev_fork, 0);

    zero_kernel<<<gNodes, T, 0, g_side>>>();
    count_deg_kernel<<<gEdges, T, 0, g_side>>>(dst);
    scan_local_kernel<<<NB_SCAN, T, 0, g_side>>>();
    scan_block_kernel<<<1, T, 0, g_side>>>();
    fill_csr_kernel<<<gEdges, T, 0, g_side>>>(src, dst);
    cudaEventRecord(g_ev_join, g_side);

    // Main stream: Layer 1 GEMM (fp16 output only)
    gemm_bf16x3<<<gGemm, T>>>(x, W1, H16, N_NODES, F_IN);

    cudaStreamWaitEvent(0, g_ev_join, 0);
    gather_relu_kernel<<<gWarp2, T>>>((const uint4*)H16, B0, b1);

    // Layer 2: GEMM reads fp32 B0, writes fp16 H16; fused gather + heads
    gemm_bf16x3<<<gGemm, T>>>(B0, W2, H16, N_NODES, HDIM);
    gather_final_kernel<<<gWarp2, T>>>((const uint4*)H16, b2, Wh1, bh1, Wh2, bh2,
                                       out1, out2, outh);

    (void)in_sizes; (void)n_in; (void)out_size;
}

// round 13
// speedup vs baseline: 1.0480x; 1.0480x over previous
#include <cuda_runtime.h>
#include <cuda_bf16.h>
#include <cuda_fp16.h>

#define N_NODES 50000
#define N_EDGES 800000
#define F_IN    256
#define HDIM    128
#define NB_SCAN ((N_NODES + 255) / 256)   // 196

// Scratch (device globals)
__device__ float  g_buf0[N_NODES * HDIM];               // fp32 intermediate
__device__ __align__(16) __half g_h16[N_NODES * HDIM];  // fp16 GEMM output
__device__ int    g_deg[N_NODES];
__device__ int    g_rowptr[N_NODES];
__device__ int    g_cursor[N_NODES];
__device__ int    g_csrsrc[N_EDGES];
__device__ float  g_dinv[N_NODES];
__device__ int    g_bsum[256];

// Side stream + fork/join events, created once at static init.
static cudaStream_t g_side = nullptr;
static cudaEvent_t  g_ev_fork = nullptr, g_ev_join = nullptr;
namespace {
struct StreamInit {
    StreamInit() {
        cudaStreamCreateWithFlags(&g_side, cudaStreamNonBlocking);
        cudaEventCreateWithFlags(&g_ev_fork, cudaEventDisableTiming);
        cudaEventCreateWithFlags(&g_ev_join, cudaEventDisableTiming);
    }
};
static StreamInit g_stream_init;
}

// ---------------------------------------------------------------- degree
__global__ void zero_kernel() {
    int i = blockIdx.x * blockDim.x + threadIdx.x;
    if (i < N_NODES) g_deg[i] = 0;
}

__global__ void count_deg_kernel(const int* __restrict__ dst) {
    int i = blockIdx.x * blockDim.x + threadIdx.x;
    if (i < N_EDGES) atomicAdd(&g_deg[dst[i]], 1);
}

// ------------------------------------------------- scan (2 kernels)
__global__ void __launch_bounds__(256) scan_local_kernel() {
    __shared__ int wsum[8];
    int tid = threadIdx.x, lane = tid & 31, wid = tid >> 5;
    int i = blockIdx.x * 256 + tid;
    int v = (i < N_NODES) ? g_deg[i] : 0;
    if (i < N_NODES) {
        g_dinv[i] = rsqrtf((float)(v + 1));
        g_cursor[i] = 0;
    }
    int incl = v;
#pragma unroll
    for (int off = 1; off < 32; off <<= 1) {
        int t = __shfl_up_sync(0xffffffffu, incl, off);
        if (lane >= off) incl += t;
    }
    if (lane == 31) wsum[wid] = incl;
    __syncthreads();
    if (wid == 0 && lane < 8) {
        int w = wsum[lane];
#pragma unroll
        for (int off = 1; off < 8; off <<= 1) {
            int t = __shfl_up_sync(0xffu, w, off);
            if (lane >= off) w += t;
        }
        wsum[lane] = w;
    }
    __syncthreads();
    int excl = incl - v + (wid ? wsum[wid - 1] : 0);
    if (i < N_NODES) g_rowptr[i] = excl;   // block-local exclusive
    if (tid == 255) g_bsum[blockIdx.x] = wsum[7];
}

__global__ void __launch_bounds__(256) scan_block_kernel() {
    __shared__ int wsum[8];
    int tid = threadIdx.x, lane = tid & 31, wid = tid >> 5;
    int v = (tid < NB_SCAN) ? g_bsum[tid] : 0;
    int incl = v;
#pragma unroll
    for (int off = 1; off < 32; off <<= 1) {
        int t = __shfl_up_sync(0xffffffffu, incl, off);
        if (lane >= off) incl += t;
    }
    if (lane == 31) wsum[wid] = incl;
    __syncthreads();
    if (wid == 0 && lane < 8) {
        int w = wsum[lane];
#pragma unroll
        for (int off = 1; off < 8; off <<= 1) {
            int t = __shfl_up_sync(0xffu, w, off);
            if (lane >= off) w += t;
        }
        wsum[lane] = w;
    }
    __syncthreads();
    int excl = incl - v + (wid ? wsum[wid - 1] : 0);
    if (tid < NB_SCAN) g_bsum[tid] = excl;
}

__global__ void fill_csr_kernel(const int* __restrict__ src,
                                const int* __restrict__ dst) {
    int i = blockIdx.x * blockDim.x + threadIdx.x;
    if (i < N_EDGES) {
        int d = dst[i];
        int pos = g_rowptr[d] + g_bsum[d >> 8] + atomicAdd(&g_cursor[d], 1);
        g_csrsrc[pos] = src[i];
    }
}

__device__ __forceinline__ int row_start(int node) {
    return g_rowptr[node] + g_bsum[node >> 8];
}

// ---------------------------------------------------------------- MMA GEMM
// C16[M,128] (fp16) = A[M,K] @ B[K,128] fp32, via bf16 2-split (3 MMAs).

__device__ __forceinline__ void ldsm4(unsigned& r0, unsigned& r1,
                                      unsigned& r2, unsigned& r3,
                                      const void* p) {
    unsigned a = (unsigned)__cvta_generic_to_shared(p);
    asm volatile("ldmatrix.sync.aligned.m8n8.x4.shared.b16 {%0,%1,%2,%3}, [%4];"
                 : "=r"(r0), "=r"(r1), "=r"(r2), "=r"(r3) : "r"(a));
}

__device__ __forceinline__ void ldsm4t(unsigned& r0, unsigned& r1,
                                       unsigned& r2, unsigned& r3,
                                       const void* p) {
    unsigned a = (unsigned)__cvta_generic_to_shared(p);
    asm volatile("ldmatrix.sync.aligned.m8n8.x4.trans.shared.b16 {%0,%1,%2,%3}, [%4];"
                 : "=r"(r0), "=r"(r1), "=r"(r2), "=r"(r3) : "r"(a));
}

__device__ __forceinline__ void mma16816(float* d, const unsigned* a,
                                         unsigned b0, unsigned b1) {
    asm volatile(
        "mma.sync.aligned.m16n8k16.row.col.f32.bf16.bf16.f32 "
        "{%0,%1,%2,%3}, {%4,%5,%6,%7}, {%8,%9}, {%0,%1,%2,%3};\n"
        : "+f"(d[0]), "+f"(d[1]), "+f"(d[2]), "+f"(d[3])
        : "r"(a[0]), "r"(a[1]), "r"(a[2]), "r"(a[3]), "r"(b0), "r"(b1));
}

__device__ __forceinline__ void split2(float x, float y,
                                       __nv_bfloat162& hi, __nv_bfloat162& lo) {
    __nv_bfloat16 hx = __float2bfloat16(x);
    __nv_bfloat16 hy = __float2bfloat16(y);
    __nv_bfloat16 lx = __float2bfloat16(x - __bfloat162float(hx));
    __nv_bfloat16 ly = __float2bfloat16(y - __bfloat162float(hy));
    hi = __halves2bfloat162(hx, hy);
    lo = __halves2bfloat162(lx, ly);
}

#define SA_LD 24   // 16 + 8 pad
#define SB_LD 136  // 128 + 8 pad

__global__ void __launch_bounds__(256) gemm_bf16x3(
    const float* __restrict__ A, const float* __restrict__ B,
    __half* __restrict__ C16, int M, int K)
{
    __shared__ __align__(16) __nv_bfloat16 sAh[2][128][SA_LD];
    __shared__ __align__(16) __nv_bfloat16 sAl[2][128][SA_LD];
    __shared__ __align__(16) __nv_bfloat16 sBh[2][16][SB_LD];
    __shared__ __align__(16) __nv_bfloat16 sBl[2][16][SB_LD];

    const int tid  = threadIdx.x;
    const int lane = tid & 31;
    const int wid  = tid >> 5;
    const int bm   = blockIdx.x * 128;

    const int wm = (wid >> 1) * 32;
    const int wn = (wid & 1) * 64;

    const int arow = tid >> 1;
    const int acg  = (tid & 1) * 8;
    const int brow = tid >> 4;
    const int bcg  = (tid & 15) * 8;

    const bool avalid = (bm + arow) < M;

    const int a_r = ((lane >> 3) & 1) * 8 + (lane & 7);
    const int a_c = (lane >> 4) * 8;
    const int b_k = ((lane >> 3) & 1) * 8 + (lane & 7);
    const int b_n = (lane >> 4) * 8;

    float acc[2][8][4];
#pragma unroll
    for (int i = 0; i < 2; i++)
#pragma unroll
        for (int j = 0; j < 8; j++)
#pragma unroll
            for (int q = 0; q < 4; q++) acc[i][j][q] = 0.0f;

    const int nt = K >> 4;

    {
        float4 a0 = make_float4(0.f,0.f,0.f,0.f), a1 = a0;
        if (avalid) {
            a0 = *(const float4*)(A + (size_t)(bm + arow) * K + acg);
            a1 = *(const float4*)(A + (size_t)(bm + arow) * K + acg + 4);
        }
        float4 b0 = *(const float4*)(B + (size_t)brow * 128 + bcg);
        float4 b1 = *(const float4*)(B + (size_t)brow * 128 + bcg + 4);
        __nv_bfloat162 h, l;
        split2(a0.x, a0.y, h, l);
        *(__nv_bfloat162*)&sAh[0][arow][acg+0] = h; *(__nv_bfloat162*)&sAl[0][arow][acg+0] = l;
        split2(a0.z, a0.w, h, l);
        *(__nv_bfloat162*)&sAh[0][arow][acg+2] = h; *(__nv_bfloat162*)&sAl[0][arow][acg+2] = l;
        split2(a1.x, a1.y, h, l);
        *(__nv_bfloat162*)&sAh[0][arow][acg+4] = h; *(__nv_bfloat162*)&sAl[0][arow][acg+4] = l;
        split2(a1.z, a1.w, h, l);
        *(__nv_bfloat162*)&sAh[0][arow][acg+6] = h; *(__nv_bfloat162*)&sAl[0][arow][acg+6] = l;
        split2(b0.x, b0.y, h, l);
        *(__nv_bfloat162*)&sBh[0][brow][bcg+0] = h; *(__nv_bfloat162*)&sBl[0][brow][bcg+0] = l;
        split2(b0.z, b0.w, h, l);
        *(__nv_bfloat162*)&sBh[0][brow][bcg+2] = h; *(__nv_bfloat162*)&sBl[0][brow][bcg+2] = l;
        split2(b1.x, b1.y, h, l);
        *(__nv_bfloat162*)&sBh[0][brow][bcg+4] = h; *(__nv_bfloat162*)&sBl[0][brow][bcg+4] = l;
        split2(b1.z, b1.w, h, l);
        *(__nv_bfloat162*)&sBh[0][brow][bcg+6] = h; *(__nv_bfloat162*)&sBl[0][brow][bcg+6] = l;
    }
    __syncthreads();

    for (int t = 0; t < nt; t++) {
        const int cur = t & 1;

        float4 a0, a1, b0, b1;
        const bool more = (t + 1) < nt;
        if (more) {
            int k0 = (t + 1) << 4;
            a0 = make_float4(0.f,0.f,0.f,0.f); a1 = a0;
            if (avalid) {
                a0 = *(const float4*)(A + (size_t)(bm + arow) * K + k0 + acg);
                a1 = *(const float4*)(A + (size_t)(bm + arow) * K + k0 + acg + 4);
            }
            b0 = *(const float4*)(B + (size_t)(k0 + brow) * 128 + bcg);
            b1 = *(const float4*)(B + (size_t)(k0 + brow) * 128 + bcg + 4);
        }

        unsigned ah[2][4], al[2][4];
#pragma unroll
        for (int tm = 0; tm < 2; tm++) {
            ldsm4(ah[tm][0], ah[tm][1], ah[tm][2], ah[tm][3],
                  &sAh[cur][wm + tm*16 + a_r][a_c]);
            ldsm4(al[tm][0], al[tm][1], al[tm][2], al[tm][3],
                  &sAl[cur][wm + tm*16 + a_r][a_c]);
        }
#pragma unroll
        for (int np = 0; np < 4; np++) {
            unsigned bh[4], bl[4];
            int n0 = wn + np * 16;
            ldsm4t(bh[0], bh[1], bh[2], bh[3], &sBh[cur][b_k][n0 + b_n]);
            ldsm4t(bl[0], bl[1], bl[2], bl[3], &sBl[cur][b_k][n0 + b_n]);
#pragma unroll
            for (int tm = 0; tm < 2; tm++) {
#pragma unroll
                for (int h = 0; h < 2; h++) {
                    float* d = acc[tm][np * 2 + h];
                    mma16816(d, ah[tm], bh[2*h], bh[2*h + 1]);
                    mma16816(d, ah[tm], bl[2*h], bl[2*h + 1]);
                    mma16816(d, al[tm], bh[2*h], bh[2*h + 1]);
                }
            }
        }

        if (more) {
            const int nxt = cur ^ 1;
            __nv_bfloat162 h, l;
            split2(a0.x, a0.y, h, l);
            *(__nv_bfloat162*)&sAh[nxt][arow][acg+0] = h; *(__nv_bfloat162*)&sAl[nxt][arow][acg+0] = l;
            split2(a0.z, a0.w, h, l);
            *(__nv_bfloat162*)&sAh[nxt][arow][acg+2] = h; *(__nv_bfloat162*)&sAl[nxt][arow][acg+2] = l;
            split2(a1.x, a1.y, h, l);
            *(__nv_bfloat162*)&sAh[nxt][arow][acg+4] = h; *(__nv_bfloat162*)&sAl[nxt][arow][acg+4] = l;
            split2(a1.z, a1.w, h, l);
            *(__nv_bfloat162*)&sAh[nxt][arow][acg+6] = h; *(__nv_bfloat162*)&sAl[nxt][arow][acg+6] = l;
            split2(b0.x, b0.y, h, l);
            *(__nv_bfloat162*)&sBh[nxt][brow][bcg+0] = h; *(__nv_bfloat162*)&sBl[nxt][brow][bcg+0] = l;
            split2(b0.z, b0.w, h, l);
            *(__nv_bfloat162*)&sBh[nxt][brow][bcg+2] = h; *(__nv_bfloat162*)&sBl[nxt][brow][bcg+2] = l;
            split2(b1.x, b1.y, h, l);
            *(__nv_bfloat162*)&sBh[nxt][brow][bcg+4] = h; *(__nv_bfloat162*)&sBl[nxt][brow][bcg+4] = l;
            split2(b1.z, b1.w, h, l);
            *(__nv_bfloat162*)&sBh[nxt][brow][bcg+6] = h; *(__nv_bfloat162*)&sBl[nxt][brow][bcg+6] = l;
        }
        __syncthreads();
    }

    const int g = lane >> 2;
    const int tq = lane & 3;
#pragma unroll
    for (int tm = 0; tm < 2; tm++) {
        int r0 = bm + wm + tm * 16 + g;
        int r1 = r0 + 8;
#pragma unroll
        for (int n8 = 0; n8 < 8; n8++) {
            int col = wn + n8 * 8 + tq * 2;
            float* d = acc[tm][n8];
            if (r0 < M)
                *(__half2*)(C16 + (size_t)r0 * 128 + col) = __floats2half2_rn(d[0], d[1]);
            if (r1 < M)
                *(__half2*)(C16 + (size_t)r1 * 128 + col) = __floats2half2_rn(d[2], d[3]);
        }
    }
}

// ---------------------------------------------------------------- gather
// One node per warp, 32 lanes; all rows (self + neighbors) read as fp16 uint2.

__global__ void gather_relu_kernel(const uint2* __restrict__ h16,  // [N][32]
                                   float* __restrict__ out,
                                   const float* __restrict__ bias)
{
    int node = (blockIdx.x * blockDim.x + threadIdx.x) >> 5;
    if (node >= N_NODES) return;
    int lane = threadIdx.x & 31;

    float dd = g_dinv[node];
    float w0 = dd * dd;
    uint2 u0 = __ldg(h16 + (size_t)node * 32 + lane);
    float2 s0 = __half22float2(*(__half2*)&u0.x);
    float2 s1 = __half22float2(*(__half2*)&u0.y);
    float4 acc = make_float4(s0.x * w0, s0.y * w0, s1.x * w0, s1.y * w0);

    int start = row_start(node);
    int cnt   = g_deg[node];

    for (int base = 0; base < cnt; base += 32) {
        int n = cnt - base; if (n > 32) n = 32;
        int s = 0; float nm = 0.f;
        if (lane < n) {
            s  = __ldg(g_csrsrc + start + base + lane);
            nm = g_dinv[s] * dd;
        }
#pragma unroll 8
        for (int j = 0; j < n; j++) {
            int   sj = __shfl_sync(0xffffffffu, s,  j);
            float nj = __shfl_sync(0xffffffffu, nm, j);
            uint2 u = __ldg(h16 + (size_t)sj * 32 + lane);
            float2 f0 = __half22float2(*(__half2*)&u.x);
            float2 f1 = __half22float2(*(__half2*)&u.y);
            acc.x += f0.x * nj; acc.y += f0.y * nj;
            acc.z += f1.x * nj; acc.w += f1.y * nj;
        }
    }

    int c = lane << 2;
    acc.x = fmaxf(acc.x + __ldg(bias + c + 0), 0.f);
    acc.y = fmaxf(acc.y + __ldg(bias + c + 1), 0.f);
    acc.z = fmaxf(acc.z + __ldg(bias + c + 2), 0.f);
    acc.w = fmaxf(acc.w + __ldg(bias + c + 3), 0.f);
    *(float4*)(out + (size_t)node * 128 + c) = acc;
}

// ------------------------------------------- gather L2 + finalize (fused)
__global__ void gather_final_kernel(const uint2* __restrict__ h16,
                                    const float* __restrict__ b2,
                                    const float* __restrict__ Wh1,
                                    const float* __restrict__ bh1,
                                    const float* __restrict__ Wh2,
                                    const float* __restrict__ bh2,
                                    float* __restrict__ out1,
                                    float* __restrict__ out2,
                                    float* __restrict__ outh)
{
    int node = (blockIdx.x * blockDim.x + threadIdx.x) >> 5;
    if (node >= N_NODES) return;
    int lane = threadIdx.x & 31;

    float dd = g_dinv[node];
    float w0 = dd * dd;
    uint2 u0 = __ldg(h16 + (size_t)node * 32 + lane);
    float2 s0 = __half22float2(*(__half2*)&u0.x);
    float2 s1 = __half22float2(*(__half2*)&u0.y);
    float4 acc = make_float4(s0.x * w0, s0.y * w0, s1.x * w0, s1.y * w0);

    int start = row_start(node);
    int cnt   = g_deg[node];

    for (int base = 0; base < cnt; base += 32) {
        int n = cnt - base; if (n > 32) n = 32;
        int s = 0; float nm = 0.f;
        if (lane < n) {
            s  = __ldg(g_csrsrc + start + base + lane);
            nm = g_dinv[s] * dd;
        }
#pragma unroll 8
        for (int j = 0; j < n; j++) {
            int   sj = __shfl_sync(0xffffffffu, s,  j);
            float nj = __shfl_sync(0xffffffffu, nm, j);
            uint2 u = __ldg(h16 + (size_t)sj * 32 + lane);
            float2 f0 = __half22float2(*(__half2*)&u.x);
            float2 f1 = __half22float2(*(__half2*)&u.y);
            acc.x += f0.x * nj; acc.y += f0.y * nj;
            acc.z += f1.x * nj; acc.w += f1.y * nj;
        }
    }

    int c = lane << 2;
    acc.x += __ldg(b2 + c + 0);
    acc.y += __ldg(b2 + c + 1);
    acc.z += __ldg(b2 + c + 2);
    acc.w += __ldg(b2 + c + 3);
    *(float4*)(outh + (size_t)node * 128 + c) = acc;

    float p[7];
#pragma unroll
    for (int j = 0; j < 4; j++) {
        p[j] = acc.x * __ldg(Wh1 + (c + 0) * 4 + j)
             + acc.y * __ldg(Wh1 + (c + 1) * 4 + j)
             + acc.z * __ldg(Wh1 + (c + 2) * 4 + j)
             + acc.w * __ldg(Wh1 + (c + 3) * 4 + j);
    }
#pragma unroll
    for (int j = 0; j < 3; j++) {
        p[4 + j] = acc.x * __ldg(Wh2 + (c + 0) * 3 + j)
                 + acc.y * __ldg(Wh2 + (c + 1) * 3 + j)
                 + acc.z * __ldg(Wh2 + (c + 2) * 3 + j)
                 + acc.w * __ldg(Wh2 + (c + 3) * 3 + j);
    }
#pragma unroll
    for (int j = 0; j < 7; j++) {
#pragma unroll
        for (int off = 16; off > 0; off >>= 1)
            p[j] += __shfl_xor_sync(0xffffffffu, p[j], off);
    }
    if (lane == 0) {
#pragma unroll
        for (int j = 0; j < 4; j++) out1[(size_t)node * 4 + j] = p[j] + __ldg(bh1 + j);
#pragma unroll
        for (int j = 0; j < 3; j++) out2[(size_t)node * 3 + j] = p[4 + j] + __ldg(bh2 + j);
    }
}

// ---------------------------------------------------------------- launch
extern "C" void kernel_launch(void* const* d_in, const int* in_sizes, int n_in,
                              void* d_out, int out_size)
{
    const float* x   = (const float*)d_in[0];
    const int*   ei  = (const int*)d_in[1];        // [2, E]
    const float* W1  = (const float*)d_in[2];
    const float* b1  = (const float*)d_in[3];
    const float* W2  = (const float*)d_in[4];
    const float* b2  = (const float*)d_in[5];
    const float* Wh1 = (const float*)d_in[6];
    const float* bh1 = (const float*)d_in[7];
    const float* Wh2 = (const float*)d_in[8];
    const float* bh2 = (const float*)d_in[9];

    const int* src = ei;
    const int* dst = ei + N_EDGES;

    float* out  = (float*)d_out;
    float* out1 = out;                                    // [N, 4]
    float* out2 = out + (size_t)N_NODES * 4;              // [N, 3]
    float* outh = out + (size_t)N_NODES * 7;              // [N, 128]

    float* B0;   cudaGetSymbolAddress((void**)&B0, g_buf0);
    __half* H16; cudaGetSymbolAddress((void**)&H16, g_h16);

    const int T = 256;
    int gNodes = (N_NODES + T - 1) / T;
    int gEdges = (N_EDGES + T - 1) / T;
    int gWarpN = (N_NODES * 32 + T - 1) / T;
    int gGemm  = (N_NODES + 127) / 128;

    // Fork: CSR build on side stream, GEMM1 on main stream (independent).
    cudaEventRecord(g_ev_fork, 0);
    cudaStreamWaitEvent(g_side, g_ev_fork, 0);

    zero_kernel<<<gNodes, T, 0, g_side>>>();
    count_deg_kernel<<<gEdges, T, 0, g_side>>>(dst);
    scan_local_kernel<<<NB_SCAN, T, 0, g_side>>>();
    scan_block_kernel<<<1, T, 0, g_side>>>();
    fill_csr_kernel<<<gEdges, T, 0, g_side>>>(src, dst);
    cudaEventRecord(g_ev_join, g_side);

    // Main stream: Layer 1 GEMM (fp16 output only)
    gemm_bf16x3<<<gGemm, T>>>(x, W1, H16, N_NODES, F_IN);

    cudaStreamWaitEvent(0, g_ev_join, 0);
    gather_relu_kernel<<<gWarpN, T>>>((const uint2*)H16, B0, b1);

    // Layer 2: GEMM reads fp32 B0, writes fp16 H16; fused gather + heads
    gemm_bf16x3<<<gGemm, T>>>(B0, W2, H16, N_NODES, HDIM);
    gather_final_kernel<<<gWarpN, T>>>((const uint2*)H16, b2, Wh1, bh1, Wh2, bh2,
                                       out1, out2, outh);

    (void)in_sizes; (void)n_in; (void)out_size;
}